// round 5
// baseline (speedup 1.0000x reference)
#include <cuda_runtime.h>
#include <cuda_bf16.h>
#include <math.h>
#include <stdint.h>

// Problem constants
#define BB    64      // batch
#define SS    512     // seq len
#define EMBD  512
#define HID   1024
#define NOUT  2

// Persistent recurrent kernel config
#define NB    128     // persistent blocks (1 block/SM, single wave)
#define TPB   256
#define JW    8       // HID / NB columns per block

// ---------------------------------------------------------------------------
// Device globals (scratch; allocation-free rule)
// ---------------------------------------------------------------------------
__device__ float g_xe0[(size_t)SS * HID * BB];  // [t][j][b]  precomputed x@W_ih0+b_hh0
__device__ float g_h0[2][HID * BB];             // [k][b] transposed h state, ping-pong
__device__ float g_h1[2][HID * BB];
__device__ unsigned g_bar;
__device__ unsigned g_gen;

// ---------------------------------------------------------------------------
// Packed fp32x2 FMA (sm_100a)
// ---------------------------------------------------------------------------
__device__ __forceinline__ void ffma2(unsigned long long& d,
                                      unsigned long long a,
                                      unsigned long long b) {
    asm("fma.rn.f32x2 %0, %1, %2, %0;" : "+l"(d) : "l"(a), "l"(b));
}
__device__ __forceinline__ unsigned long long bcast2(float v) {
    unsigned long long r;
    asm("mov.b64 %0, {%1, %1};" : "=l"(r) : "f"(v));
    return r;
}

// ---------------------------------------------------------------------------
// Software grid barrier (all NB blocks resident in one wave)
// ---------------------------------------------------------------------------
__device__ __forceinline__ void grid_sync() {
    __threadfence();
    __syncthreads();
    if (threadIdx.x == 0) {
        volatile unsigned* genp = &g_gen;
        unsigned my = *genp;
        if (atomicAdd(&g_bar, 1u) == NB - 1) {
            atomicExch(&g_bar, 0u);
            __threadfence();
            atomicAdd(&g_gen, 1u);
        } else {
            while (*genp == my) { __nanosleep(32); }
        }
    }
    __syncthreads();
}

// ---------------------------------------------------------------------------
// Kernel 1: xe0[t][j][b] = sum_e emb[x[b][t]][e] * W_ih0[e][j] + b_hh0[j]
// ---------------------------------------------------------------------------
__global__ void __launch_bounds__(256)
emb_gemm_kernel(const int* __restrict__ x, const float* __restrict__ emb,
                const float* __restrict__ Wih0, const float* __restrict__ bhh0) {
    __shared__ float As[64][17];
    __shared__ float Bs[16][64];
    __shared__ int   ids[64];

    const int t   = blockIdx.x;
    const int j0  = blockIdx.y * 64;
    const int tid = threadIdx.x;

    if (tid < 64) ids[tid] = x[tid * SS + t];
    __syncthreads();

    const int ty = tid >> 4;
    const int tx = tid & 15;
    float acc[4][4];
    #pragma unroll
    for (int i = 0; i < 4; i++)
        #pragma unroll
        for (int j = 0; j < 4; j++) acc[i][j] = 0.f;

    for (int k0 = 0; k0 < EMBD; k0 += 16) {
        #pragma unroll
        for (int p = 0; p < 4; p++) {
            int r  = (tid >> 4) + p * 16;
            int kk = tid & 15;
            As[r][kk] = emb[(size_t)ids[r] * EMBD + k0 + kk];
        }
        #pragma unroll
        for (int p = 0; p < 4; p++) {
            int kk = (tid >> 6) + p * 4;
            int c  = tid & 63;
            Bs[kk][c] = Wih0[(size_t)(k0 + kk) * HID + j0 + c];
        }
        __syncthreads();
        #pragma unroll
        for (int kk = 0; kk < 16; kk++) {
            float a0 = As[ty * 4 + 0][kk];
            float a1 = As[ty * 4 + 1][kk];
            float a2 = As[ty * 4 + 2][kk];
            float a3 = As[ty * 4 + 3][kk];
            float4 bv = *reinterpret_cast<const float4*>(&Bs[kk][tx * 4]);
            float bw[4] = {bv.x, bv.y, bv.z, bv.w};
            #pragma unroll
            for (int j = 0; j < 4; j++) {
                acc[0][j] = fmaf(a0, bw[j], acc[0][j]);
                acc[1][j] = fmaf(a1, bw[j], acc[1][j]);
                acc[2][j] = fmaf(a2, bw[j], acc[2][j]);
                acc[3][j] = fmaf(a3, bw[j], acc[3][j]);
            }
        }
        __syncthreads();
    }

    #pragma unroll
    for (int j = 0; j < 4; j++) {
        int col = j0 + tx * 4 + j;
        float bias = bhh0[col];
        float4 v;
        v.x = acc[0][j] + bias;
        v.y = acc[1][j] + bias;
        v.z = acc[2][j] + bias;
        v.w = acc[3][j] + bias;
        *reinterpret_cast<float4*>(&g_xe0[((size_t)t * HID + col) * BB + ty * 4]) = v;
    }
}

// ---------------------------------------------------------------------------
// Kernel 2: persistent fused-pipeline recurrent kernel.
// One tick τ computes BOTH  h0(τ)   = tanh(xe0[τ] + h0(τ-1)@W_hh0)
//                    and    h1(τ-1) = tanh(h0(τ-1)@W_ih1 + h1(τ-2)@W_hh1 + b)
// sharing the single h0(τ-1) load, with ONE grid barrier per tick.
// 513 ticks total; L1 store gated at τ=0, L0 store gated at τ=SS.
// ---------------------------------------------------------------------------
#define SMEM_FLOATS (3 * HID * JW + TPB * 32)
#define SMEM_BYTES  (SMEM_FLOATS * 4)

__global__ void __launch_bounds__(TPB, 1)
rnn_kernel(const float* __restrict__ Whh0, const float* __restrict__ Wih1,
           const float* __restrict__ Whh1, const float* __restrict__ bhh1) {
    extern __shared__ float smem[];
    float* ws0  = smem;                    // W_hh0 slice [k][8]
    float* ws1i = smem + HID * JW;         // W_ih1 slice
    float* ws1h = smem + 2 * HID * JW;     // W_hh1 slice
    float* red  = smem + 3 * HID * JW;     // [tid][32] reduction scratch

    const int tid = threadIdx.x;
    const int bid = blockIdx.x;
    const int jg  = bid * JW;

    for (int i = tid; i < HID * JW; i += TPB) {
        int k = i >> 3, jj = i & 7;
        ws0[i]  = Whh0[(size_t)k * HID + jg + jj];
        ws1i[i] = Wih1[(size_t)k * HID + jg + jj];
        ws1h[i] = Whh1[(size_t)k * HID + jg + jj];
    }
    // Zero all four h buffers (both parities)
    for (int i = bid * TPB + tid; i < HID * BB; i += NB * TPB) {
        g_h0[0][i] = 0.f; g_h0[1][i] = 0.f;
        g_h1[0][i] = 0.f; g_h1[1][i] = 0.f;
    }
    grid_sync();

    const int bq = tid & 15;   // batch quad
    const int kc = tid >> 4;   // K-chunk (16 chunks of 64)
    const int k0 = kc * 64;

    for (int t = 0; t <= SS; t++) {
        const int p = t & 1;
        const int q = p ^ 1;
        const float* h0r = g_h0[p];   // h0(t-1)
        const float* h1r = g_h1[p];   // h1(t-2)
        float*       h0w = g_h0[q];   // h0(t)
        float*       h1w = g_h1[q];   // h1(t-1)

        unsigned long long a0[4][4], a1[4][4];
        #pragma unroll
        for (int b = 0; b < 4; b++)
            #pragma unroll
            for (int jp = 0; jp < 4; jp++) { a0[b][jp] = 0ull; a1[b][jp] = 0ull; }

        #pragma unroll 2
        for (int k = k0; k < k0 + 64; k++) {
            float4 hv0 = __ldcg(reinterpret_cast<const float4*>(h0r + k * BB + bq * 4));
            float4 hv1 = __ldcg(reinterpret_cast<const float4*>(h1r + k * BB + bq * 4));
            const unsigned long long* wp0 =
                reinterpret_cast<const unsigned long long*>(ws0 + k * 8);
            const unsigned long long* wpi =
                reinterpret_cast<const unsigned long long*>(ws1i + k * 8);
            const unsigned long long* wph =
                reinterpret_cast<const unsigned long long*>(ws1h + k * 8);
            unsigned long long h0p[4] = {bcast2(hv0.x), bcast2(hv0.y),
                                         bcast2(hv0.z), bcast2(hv0.w)};
            unsigned long long h1p[4] = {bcast2(hv1.x), bcast2(hv1.y),
                                         bcast2(hv1.z), bcast2(hv1.w)};
            #pragma unroll
            for (int jp = 0; jp < 4; jp++) {
                unsigned long long w0 = wp0[jp];
                unsigned long long wi = wpi[jp];
                unsigned long long wh = wph[jp];
                #pragma unroll
                for (int b = 0; b < 4; b++) {
                    ffma2(a0[b][jp], h0p[b], w0);   // layer-0 GEMM
                    ffma2(a1[b][jp], h0p[b], wi);   // layer-1: h0 @ W_ih1
                    ffma2(a1[b][jp], h1p[b], wh);   // layer-1: h1 @ W_hh1
                }
            }
        }

        // ---- epilogue L0: h0(t) = tanh(xe0[t] + sum) ----
        #pragma unroll
        for (int b = 0; b < 4; b++)
            #pragma unroll
            for (int jp = 0; jp < 4; jp++)
                *reinterpret_cast<unsigned long long*>(
                    red + tid * 32 + b * 8 + jp * 2) = a0[b][jp];
        __syncthreads();
        {
            const int tl = (t < SS) ? t : (SS - 1);
            #pragma unroll
            for (int o = tid; o < BB * JW; o += TPB) {   // 2 outputs/thread
                int b = o & 63, jj = o >> 6;
                int bq2 = b >> 2, bb2 = b & 3;
                float s = 0.f;
                #pragma unroll
                for (int kk = 0; kk < 16; kk++)
                    s += red[((kk << 4) + bq2) * 32 + bb2 * 8 + jj];
                s += g_xe0[((size_t)tl * HID + jg + jj) * BB + b];
                if (t < SS)
                    __stcg(h0w + (jg + jj) * BB + b, tanhf(s));
            }
        }
        __syncthreads();

        // ---- epilogue L1: h1(t-1) = tanh(sum + b_hh1) ----
        #pragma unroll
        for (int b = 0; b < 4; b++)
            #pragma unroll
            for (int jp = 0; jp < 4; jp++)
                *reinterpret_cast<unsigned long long*>(
                    red + tid * 32 + b * 8 + jp * 2) = a1[b][jp];
        __syncthreads();
        #pragma unroll
        for (int o = tid; o < BB * JW; o += TPB) {
            int b = o & 63, jj = o >> 6;
            int bq2 = b >> 2, bb2 = b & 3;
            float s = 0.f;
            #pragma unroll
            for (int kk = 0; kk < 16; kk++)
                s += red[((kk << 4) + bq2) * 32 + bb2 * 8 + jj];
            s += bhh1[jg + jj];
            if (t > 0)
                __stcg(h1w + (jg + jj) * BB + b, tanhf(s));
        }

        grid_sync();
    }
}

// ---------------------------------------------------------------------------
// Kernel 3: out[b][o] = h1_final[.][b] . W_out[.][o] + b_out[o]
// h1(511) is written at tick t=512 into buffer (512&1)^1 = 1.
// ---------------------------------------------------------------------------
__global__ void __launch_bounds__(128)
out_kernel(const float* __restrict__ Wout, const float* __restrict__ bout,
           float* __restrict__ out) {
    const int tid = threadIdx.x;
    const int b = tid & 63;
    const int o = tid >> 6;
    const float* h = g_h1[1];
    float s0 = 0.f, s1 = 0.f, s2 = 0.f, s3 = 0.f;
    #pragma unroll 4
    for (int k = 0; k < HID; k += 4) {
        s0 = fmaf(h[(k + 0) * BB + b], Wout[(size_t)(k + 0) * NOUT + o], s0);
        s1 = fmaf(h[(k + 1) * BB + b], Wout[(size_t)(k + 1) * NOUT + o], s1);
        s2 = fmaf(h[(k + 2) * BB + b], Wout[(size_t)(k + 2) * NOUT + o], s2);
        s3 = fmaf(h[(k + 3) * BB + b], Wout[(size_t)(k + 3) * NOUT + o], s3);
    }
    out[b * NOUT + o] = s0 + s1 + s2 + s3 + bout[o];
}

// ---------------------------------------------------------------------------
extern "C" void kernel_launch(void* const* d_in, const int* in_sizes, int n_in,
                              void* d_out, int out_size) {
    const int*   x    = (const int*)  d_in[0];
    const float* emb  = (const float*)d_in[1];
    const float* Wih0 = (const float*)d_in[2];
    const float* Whh0 = (const float*)d_in[3];
    const float* bhh0 = (const float*)d_in[4];
    const float* Wih1 = (const float*)d_in[5];
    const float* Whh1 = (const float*)d_in[6];
    const float* bhh1 = (const float*)d_in[7];
    const float* Wout = (const float*)d_in[8];
    const float* bout = (const float*)d_in[9];
    float* out = (float*)d_out;

    cudaFuncSetAttribute(rnn_kernel, cudaFuncAttributeMaxDynamicSharedMemorySize,
                         SMEM_BYTES);

    emb_gemm_kernel<<<dim3(SS, HID / 64), 256>>>(x, emb, Wih0, bhh0);
    rnn_kernel<<<NB, TPB, SMEM_BYTES>>>(Whh0, Wih1, Whh1, bhh1);
    out_kernel<<<1, 128>>>(Wout, bout, out);
}

// round 6
// speedup vs baseline: 1.0028x; 1.0028x over previous
#include <cuda_runtime.h>
#include <cuda_bf16.h>
#include <math.h>
#include <stdint.h>

// Problem constants
#define BB    64      // batch
#define SS    512     // seq len
#define EMBD  512
#define HID   1024
#define NOUT  2

// Persistent recurrent kernel config
#define NB    128     // persistent blocks (1 block/SM, single wave)
#define TPB   256
#define JW    8       // HID / NB columns per block

// ---------------------------------------------------------------------------
// Device globals (scratch; allocation-free rule)
// ---------------------------------------------------------------------------
__device__ float g_xe0[(size_t)SS * HID * BB];  // [t][j][b]  precomputed x@W_ih0+b_hh0
__device__ float g_h0[2][HID * BB];             // [k][b] transposed h state, ping-pong
__device__ float g_h1[2][HID * BB];
__device__ unsigned g_bar;
__device__ unsigned g_gen;

// ---------------------------------------------------------------------------
// Packed fp32x2 FMA (sm_100a)
// ---------------------------------------------------------------------------
__device__ __forceinline__ void ffma2(unsigned long long& d,
                                      unsigned long long a,
                                      unsigned long long b) {
    asm("fma.rn.f32x2 %0, %1, %2, %0;" : "+l"(d) : "l"(a), "l"(b));
}
__device__ __forceinline__ unsigned long long bcast2(float v) {
    unsigned long long r;
    asm("mov.b64 %0, {%1, %1};" : "=l"(r) : "f"(v));
    return r;
}

// ---------------------------------------------------------------------------
// Software grid barrier (all NB blocks resident in one wave)
// ---------------------------------------------------------------------------
__device__ __forceinline__ void grid_sync() {
    __threadfence();
    __syncthreads();
    if (threadIdx.x == 0) {
        volatile unsigned* genp = &g_gen;
        unsigned my = *genp;
        if (atomicAdd(&g_bar, 1u) == NB - 1) {
            atomicExch(&g_bar, 0u);
            __threadfence();
            atomicAdd(&g_gen, 1u);
        } else {
            while (*genp == my) { __nanosleep(32); }
        }
    }
    __syncthreads();
}

// ---------------------------------------------------------------------------
// Kernel 1: xe0[t][j][b] = sum_e emb[x[b][t]][e] * W_ih0[e][j] + b_hh0[j]
// ---------------------------------------------------------------------------
__global__ void __launch_bounds__(256)
emb_gemm_kernel(const int* __restrict__ x, const float* __restrict__ emb,
                const float* __restrict__ Wih0, const float* __restrict__ bhh0) {
    __shared__ float As[64][17];
    __shared__ float Bs[16][64];
    __shared__ int   ids[64];

    const int t   = blockIdx.x;
    const int j0  = blockIdx.y * 64;
    const int tid = threadIdx.x;

    if (tid < 64) ids[tid] = x[tid * SS + t];
    __syncthreads();

    const int ty = tid >> 4;
    const int tx = tid & 15;
    float acc[4][4];
    #pragma unroll
    for (int i = 0; i < 4; i++)
        #pragma unroll
        for (int j = 0; j < 4; j++) acc[i][j] = 0.f;

    for (int k0 = 0; k0 < EMBD; k0 += 16) {
        #pragma unroll
        for (int p = 0; p < 4; p++) {
            int r  = (tid >> 4) + p * 16;
            int kk = tid & 15;
            As[r][kk] = emb[(size_t)ids[r] * EMBD + k0 + kk];
        }
        #pragma unroll
        for (int p = 0; p < 4; p++) {
            int kk = (tid >> 6) + p * 4;
            int c  = tid & 63;
            Bs[kk][c] = Wih0[(size_t)(k0 + kk) * HID + j0 + c];
        }
        __syncthreads();
        #pragma unroll
        for (int kk = 0; kk < 16; kk++) {
            float a0 = As[ty * 4 + 0][kk];
            float a1 = As[ty * 4 + 1][kk];
            float a2 = As[ty * 4 + 2][kk];
            float a3 = As[ty * 4 + 3][kk];
            float4 bv = *reinterpret_cast<const float4*>(&Bs[kk][tx * 4]);
            float bw[4] = {bv.x, bv.y, bv.z, bv.w};
            #pragma unroll
            for (int j = 0; j < 4; j++) {
                acc[0][j] = fmaf(a0, bw[j], acc[0][j]);
                acc[1][j] = fmaf(a1, bw[j], acc[1][j]);
                acc[2][j] = fmaf(a2, bw[j], acc[2][j]);
                acc[3][j] = fmaf(a3, bw[j], acc[3][j]);
            }
        }
        __syncthreads();
    }

    #pragma unroll
    for (int j = 0; j < 4; j++) {
        int col = j0 + tx * 4 + j;
        float bias = bhh0[col];
        float4 v;
        v.x = acc[0][j] + bias;
        v.y = acc[1][j] + bias;
        v.z = acc[2][j] + bias;
        v.w = acc[3][j] + bias;
        *reinterpret_cast<float4*>(&g_xe0[((size_t)t * HID + col) * BB + ty * 4]) = v;
    }
}

// ---------------------------------------------------------------------------
// Kernel 2: persistent fused-pipeline recurrent kernel.
// One tick τ computes BOTH  h0(τ)   = tanh(xe0[τ] + h0(τ-1)@W_hh0)
//                    and    h1(τ-1) = tanh(h0(τ-1)@W_ih1 + h1(τ-2)@W_hh1 + b)
// sharing the single h0(τ-1) load, with ONE grid barrier per tick.
// 513 ticks total; L1 store gated at τ=0, L0 store gated at τ=SS.
// ---------------------------------------------------------------------------
#define SMEM_FLOATS (3 * HID * JW + TPB * 32)
#define SMEM_BYTES  (SMEM_FLOATS * 4)

__global__ void __launch_bounds__(TPB, 1)
rnn_kernel(const float* __restrict__ Whh0, const float* __restrict__ Wih1,
           const float* __restrict__ Whh1, const float* __restrict__ bhh1) {
    extern __shared__ float smem[];
    float* ws0  = smem;                    // W_hh0 slice [k][8]
    float* ws1i = smem + HID * JW;         // W_ih1 slice
    float* ws1h = smem + 2 * HID * JW;     // W_hh1 slice
    float* red  = smem + 3 * HID * JW;     // [tid][32] reduction scratch

    const int tid = threadIdx.x;
    const int bid = blockIdx.x;
    const int jg  = bid * JW;

    for (int i = tid; i < HID * JW; i += TPB) {
        int k = i >> 3, jj = i & 7;
        ws0[i]  = Whh0[(size_t)k * HID + jg + jj];
        ws1i[i] = Wih1[(size_t)k * HID + jg + jj];
        ws1h[i] = Whh1[(size_t)k * HID + jg + jj];
    }
    // Zero all four h buffers (both parities)
    for (int i = bid * TPB + tid; i < HID * BB; i += NB * TPB) {
        g_h0[0][i] = 0.f; g_h0[1][i] = 0.f;
        g_h1[0][i] = 0.f; g_h1[1][i] = 0.f;
    }
    grid_sync();

    const int bq = tid & 15;   // batch quad
    const int kc = tid >> 4;   // K-chunk (16 chunks of 64)
    const int k0 = kc * 64;

    for (int t = 0; t <= SS; t++) {
        const int p = t & 1;
        const int q = p ^ 1;
        const float* h0r = g_h0[p];   // h0(t-1)
        const float* h1r = g_h1[p];   // h1(t-2)
        float*       h0w = g_h0[q];   // h0(t)
        float*       h1w = g_h1[q];   // h1(t-1)

        unsigned long long a0[4][4], a1[4][4];
        #pragma unroll
        for (int b = 0; b < 4; b++)
            #pragma unroll
            for (int jp = 0; jp < 4; jp++) { a0[b][jp] = 0ull; a1[b][jp] = 0ull; }

        #pragma unroll 2
        for (int k = k0; k < k0 + 64; k++) {
            float4 hv0 = __ldcg(reinterpret_cast<const float4*>(h0r + k * BB + bq * 4));
            float4 hv1 = __ldcg(reinterpret_cast<const float4*>(h1r + k * BB + bq * 4));
            const unsigned long long* wp0 =
                reinterpret_cast<const unsigned long long*>(ws0 + k * 8);
            const unsigned long long* wpi =
                reinterpret_cast<const unsigned long long*>(ws1i + k * 8);
            const unsigned long long* wph =
                reinterpret_cast<const unsigned long long*>(ws1h + k * 8);
            unsigned long long h0p[4] = {bcast2(hv0.x), bcast2(hv0.y),
                                         bcast2(hv0.z), bcast2(hv0.w)};
            unsigned long long h1p[4] = {bcast2(hv1.x), bcast2(hv1.y),
                                         bcast2(hv1.z), bcast2(hv1.w)};
            #pragma unroll
            for (int jp = 0; jp < 4; jp++) {
                unsigned long long w0 = wp0[jp];
                unsigned long long wi = wpi[jp];
                unsigned long long wh = wph[jp];
                #pragma unroll
                for (int b = 0; b < 4; b++) {
                    ffma2(a0[b][jp], h0p[b], w0);   // layer-0 GEMM
                    ffma2(a1[b][jp], h0p[b], wi);   // layer-1: h0 @ W_ih1
                    ffma2(a1[b][jp], h1p[b], wh);   // layer-1: h1 @ W_hh1
                }
            }
        }

        // ---- epilogue L0: h0(t) = tanh(xe0[t] + sum) ----
        #pragma unroll
        for (int b = 0; b < 4; b++)
            #pragma unroll
            for (int jp = 0; jp < 4; jp++)
                *reinterpret_cast<unsigned long long*>(
                    red + tid * 32 + b * 8 + jp * 2) = a0[b][jp];
        __syncthreads();
        {
            const int tl = (t < SS) ? t : (SS - 1);
            #pragma unroll
            for (int o = tid; o < BB * JW; o += TPB) {   // 2 outputs/thread
                int b = o & 63, jj = o >> 6;
                int bq2 = b >> 2, bb2 = b & 3;
                float s = 0.f;
                #pragma unroll
                for (int kk = 0; kk < 16; kk++)
                    s += red[((kk << 4) + bq2) * 32 + bb2 * 8 + jj];
                s += g_xe0[((size_t)tl * HID + jg + jj) * BB + b];
                if (t < SS)
                    __stcg(h0w + (jg + jj) * BB + b, tanhf(s));
            }
        }
        __syncthreads();

        // ---- epilogue L1: h1(t-1) = tanh(sum + b_hh1) ----
        #pragma unroll
        for (int b = 0; b < 4; b++)
            #pragma unroll
            for (int jp = 0; jp < 4; jp++)
                *reinterpret_cast<unsigned long long*>(
                    red + tid * 32 + b * 8 + jp * 2) = a1[b][jp];
        __syncthreads();
        #pragma unroll
        for (int o = tid; o < BB * JW; o += TPB) {
            int b = o & 63, jj = o >> 6;
            int bq2 = b >> 2, bb2 = b & 3;
            float s = 0.f;
            #pragma unroll
            for (int kk = 0; kk < 16; kk++)
                s += red[((kk << 4) + bq2) * 32 + bb2 * 8 + jj];
            s += bhh1[jg + jj];
            if (t > 0)
                __stcg(h1w + (jg + jj) * BB + b, tanhf(s));
        }

        grid_sync();
    }
}

// ---------------------------------------------------------------------------
// Kernel 3: out[b][o] = h1_final[.][b] . W_out[.][o] + b_out[o]
// h1(511) is written at tick t=512 into buffer (512&1)^1 = 1.
// ---------------------------------------------------------------------------
__global__ void __launch_bounds__(128)
out_kernel(const float* __restrict__ Wout, const float* __restrict__ bout,
           float* __restrict__ out) {
    const int tid = threadIdx.x;
    const int b = tid & 63;
    const int o = tid >> 6;
    const float* h = g_h1[1];
    float s0 = 0.f, s1 = 0.f, s2 = 0.f, s3 = 0.f;
    #pragma unroll 4
    for (int k = 0; k < HID; k += 4) {
        s0 = fmaf(h[(k + 0) * BB + b], Wout[(size_t)(k + 0) * NOUT + o], s0);
        s1 = fmaf(h[(k + 1) * BB + b], Wout[(size_t)(k + 1) * NOUT + o], s1);
        s2 = fmaf(h[(k + 2) * BB + b], Wout[(size_t)(k + 2) * NOUT + o], s2);
        s3 = fmaf(h[(k + 3) * BB + b], Wout[(size_t)(k + 3) * NOUT + o], s3);
    }
    out[b * NOUT + o] = s0 + s1 + s2 + s3 + bout[o];
}

// ---------------------------------------------------------------------------
extern "C" void kernel_launch(void* const* d_in, const int* in_sizes, int n_in,
                              void* d_out, int out_size) {
    const int*   x    = (const int*)  d_in[0];
    const float* emb  = (const float*)d_in[1];
    const float* Wih0 = (const float*)d_in[2];
    const float* Whh0 = (const float*)d_in[3];
    const float* bhh0 = (const float*)d_in[4];
    const float* Wih1 = (const float*)d_in[5];
    const float* Whh1 = (const float*)d_in[6];
    const float* bhh1 = (const float*)d_in[7];
    const float* Wout = (const float*)d_in[8];
    const float* bout = (const float*)d_in[9];
    float* out = (float*)d_out;

    cudaFuncSetAttribute(rnn_kernel, cudaFuncAttributeMaxDynamicSharedMemorySize,
                         SMEM_BYTES);

    emb_gemm_kernel<<<dim3(SS, HID / 64), 256>>>(x, emb, Wih0, bhh0);
    rnn_kernel<<<NB, TPB, SMEM_BYTES>>>(Whh0, Wih1, Whh1, bhh1);
    out_kernel<<<1, 128>>>(Wout, bout, out);
}

// round 8
// speedup vs baseline: 1.5264x; 1.5222x over previous
#include <cuda_runtime.h>
#include <cuda_bf16.h>
#include <math.h>
#include <stdint.h>

#define BB    64
#define SS    512
#define EMBD  512
#define HID   1024
#define NOUT  2

#define NB      128
#define TPB     256
#define JW      8        // output cols per CTA
#define NCHUNK  16       // K chunks of 64
#define NSLOT   3

// SMEM map (bytes)
#define SM_W    0                      // B weights: 2 planes x 49152
#define WPLANE  49152                  // [kc 16][row 24][128B swizzled row]
#define SM_A    (2*WPLANE)             // 3 slots x 32768 ([plane][row128][128B row])
#define SM_SCR  (SM_A + NSLOT*32768)   // 64x8 floats
#define SMEM_BYTES (SM_SCR + 2048)

#define SWZ(o) ((uint32_t)(o) ^ ((((uint32_t)(o))>>3)&0x70))

// ---------------------------------------------------------------------------
__device__ __align__(16) float g_xe0[(size_t)SS * BB * HID];   // [t][b][j]
__device__ __align__(16) __nv_bfloat16 g_Ahi[2][128 * HID];    // rows 0-63 h0, 64-127 h1
__device__ __align__(16) __nv_bfloat16 g_Alo[2][128 * HID];
__device__ __align__(16) float g_h1fin[BB * HID];
__device__ unsigned g_bar, g_gen;

// ---------------------------------------------------------------------------
__device__ __forceinline__ uint32_t smem_u32(const void* p) {
    return (uint32_t)__cvta_generic_to_shared(p);
}
__device__ __forceinline__ void cpa16(uint32_t dst, const void* src) {
    asm volatile("cp.async.cg.shared.global [%0], [%1], 16;"
                 :: "r"(dst), "l"(__cvta_generic_to_global(src)) : "memory");
}
__device__ __forceinline__ void ldsm4(uint32_t* r, uint32_t addr) {
    asm volatile("ldmatrix.sync.aligned.m8n8.x4.shared.b16 {%0,%1,%2,%3}, [%4];"
                 : "=r"(r[0]), "=r"(r[1]), "=r"(r[2]), "=r"(r[3]) : "r"(addr));
}
__device__ __forceinline__ void ldsm2(uint32_t* r, uint32_t addr) {
    asm volatile("ldmatrix.sync.aligned.m8n8.x2.shared.b16 {%0,%1}, [%2];"
                 : "=r"(r[0]), "=r"(r[1]) : "r"(addr));
}
__device__ __forceinline__ void mma_bf16(float* c, const uint32_t* a,
                                         const uint32_t* b) {
    asm volatile(
        "mma.sync.aligned.m16n8k16.row.col.f32.bf16.bf16.f32 "
        "{%0,%1,%2,%3}, {%4,%5,%6,%7}, {%8,%9}, {%0,%1,%2,%3};"
        : "+f"(c[0]), "+f"(c[1]), "+f"(c[2]), "+f"(c[3])
        : "r"(a[0]), "r"(a[1]), "r"(a[2]), "r"(a[3]), "r"(b[0]), "r"(b[1]));
}
__device__ __forceinline__ uint32_t pack_hi2(float a, float b) {
    __nv_bfloat16 ha = __float2bfloat16(a), hb = __float2bfloat16(b);
    return (uint32_t)*reinterpret_cast<unsigned short*>(&ha)
         | ((uint32_t)*reinterpret_cast<unsigned short*>(&hb) << 16);
}
__device__ __forceinline__ uint32_t pack_lo2(float a, float b) {
    __nv_bfloat16 ha = __float2bfloat16(a), hb = __float2bfloat16(b);
    __nv_bfloat16 la = __float2bfloat16(a - __bfloat162float(ha));
    __nv_bfloat16 lb = __float2bfloat16(b - __bfloat162float(hb));
    return (uint32_t)*reinterpret_cast<unsigned short*>(&la)
         | ((uint32_t)*reinterpret_cast<unsigned short*>(&lb) << 16);
}

__device__ __forceinline__ void grid_sync() {
    __threadfence();
    __syncthreads();
    if (threadIdx.x == 0) {
        volatile unsigned* genp = &g_gen;
        unsigned my = *genp;
        if (atomicAdd(&g_bar, 1u) == NB - 1) {
            atomicExch(&g_bar, 0u);
            __threadfence();
            atomicAdd(&g_gen, 1u);
        } else {
            while (*genp == my) { __nanosleep(32); }
        }
    }
    __syncthreads();
}

// ---------------------------------------------------------------------------
// Kernel 1: xe0[t][b][j] = emb[x[b][t]] @ W_ih0 + b_hh0
// ---------------------------------------------------------------------------
__global__ void __launch_bounds__(256)
emb_gemm_kernel(const int* __restrict__ x, const float* __restrict__ emb,
                const float* __restrict__ Wih0, const float* __restrict__ bhh0) {
    __shared__ float As[64][17];
    __shared__ float Bs[16][64];
    __shared__ int   ids[64];

    const int t   = blockIdx.x;
    const int j0  = blockIdx.y * 64;
    const int tid = threadIdx.x;

    if (tid < 64) ids[tid] = x[tid * SS + t];
    __syncthreads();

    const int ty = tid >> 4;
    const int tx = tid & 15;
    float acc[4][4];
    #pragma unroll
    for (int i = 0; i < 4; i++)
        #pragma unroll
        for (int j = 0; j < 4; j++) acc[i][j] = 0.f;

    for (int k0 = 0; k0 < EMBD; k0 += 16) {
        #pragma unroll
        for (int p = 0; p < 4; p++) {
            int r  = (tid >> 4) + p * 16;
            int kk = tid & 15;
            As[r][kk] = emb[(size_t)ids[r] * EMBD + k0 + kk];
        }
        #pragma unroll
        for (int p = 0; p < 4; p++) {
            int kk = (tid >> 6) + p * 4;
            int c  = tid & 63;
            Bs[kk][c] = Wih0[(size_t)(k0 + kk) * HID + j0 + c];
        }
        __syncthreads();
        #pragma unroll
        for (int kk = 0; kk < 16; kk++) {
            float a0 = As[ty * 4 + 0][kk];
            float a1 = As[ty * 4 + 1][kk];
            float a2 = As[ty * 4 + 2][kk];
            float a3 = As[ty * 4 + 3][kk];
            float4 bv = *reinterpret_cast<const float4*>(&Bs[kk][tx * 4]);
            float bw[4] = {bv.x, bv.y, bv.z, bv.w};
            #pragma unroll
            for (int j = 0; j < 4; j++) {
                acc[0][j] = fmaf(a0, bw[j], acc[0][j]);
                acc[1][j] = fmaf(a1, bw[j], acc[1][j]);
                acc[2][j] = fmaf(a2, bw[j], acc[2][j]);
                acc[3][j] = fmaf(a3, bw[j], acc[3][j]);
            }
        }
        __syncthreads();
    }

    float4 bv = *reinterpret_cast<const float4*>(bhh0 + j0 + tx * 4);
    #pragma unroll
    for (int i = 0; i < 4; i++) {
        float4 v;
        v.x = acc[i][0] + bv.x;
        v.y = acc[i][1] + bv.y;
        v.z = acc[i][2] + bv.z;
        v.w = acc[i][3] + bv.w;
        *reinterpret_cast<float4*>(
            &g_xe0[((size_t)t * BB + (ty * 4 + i)) * HID + j0 + tx * 4]) = v;
    }
}

// ---------------------------------------------------------------------------
// Kernel 2: persistent HMMA (mma.sync bf16) recurrent kernel.
// A = [h0(t-1); h1(t-2)] (M=128), split-bf16 hi/lo planes in global.
// Per CTA: fused B = 24 rows (Whh0|Wih1|Whh1 cols jg..jg+7), SMEM-resident.
// D[nt=0] = h-rows @ Whh0 (valid rows 0-63), D[1] = @Wih1 (rows 0-63),
// D[2] = @Whh1 (rows 64-127).  3-product split: hh*Wh + hl*Wh + hh*Wl.
// ---------------------------------------------------------------------------
__global__ void __launch_bounds__(TPB, 1)
rnn_kernel(const float* __restrict__ Whh0, const float* __restrict__ Wih1,
           const float* __restrict__ Whh1, const float* __restrict__ bhh1) {
    extern __shared__ char smem[];
    const uint32_t sb = smem_u32(smem);
    float* scratch = reinterpret_cast<float*>(smem + SM_SCR);
    const int tid = threadIdx.x;
    const int wid = tid >> 5;
    const int lid = tid & 31;
    const int bid = blockIdx.x;
    const int jg  = bid * JW;

    // ---- resident weights: [plane][kc][row24][swizzled 128B row] ----
    for (int i = tid; i < 24 * HID; i += TPB) {
        int j24 = i / HID, k = i % HID;
        int m = j24 >> 3, jj = j24 & 7;
        const float* W = (m == 0) ? Whh0 : ((m == 1) ? Wih1 : Whh1);
        float w = W[(size_t)k * HID + jg + jj];
        __nv_bfloat16 hi = __float2bfloat16(w);
        __nv_bfloat16 lo = __float2bfloat16(w - __bfloat162float(hi));
        uint32_t off = (uint32_t)(k >> 6) * 3072 + SWZ((uint32_t)j24 * 128 + (k & 63) * 2);
        *reinterpret_cast<__nv_bfloat16*>(smem + SM_W + off) = hi;
        *reinterpret_cast<__nv_bfloat16*>(smem + SM_W + WPLANE + off) = lo;
    }
    // ---- zero A planes (both parities) ----
    for (int i = bid * TPB + tid; i < 128 * HID; i += NB * TPB) {
        g_Ahi[0][i] = __float2bfloat16(0.f); g_Ahi[1][i] = __float2bfloat16(0.f);
        g_Alo[0][i] = __float2bfloat16(0.f); g_Alo[1][i] = __float2bfloat16(0.f);
    }

    // per-lane epilogue constants (warps 0-3 use bias)
    const int ejj = (lid & 3) * 2;
    float2 biasv = *reinterpret_cast<const float2*>(bhh1 + jg + ejj);

    // per-lane ldmatrix offsets
    const int arow = wid * 16 + (lid & 15);           // A tile row
    const uint32_t aoff0 = (uint32_t)arow * 128 + ((uint32_t)(lid >> 4)) * 16;
    const uint32_t bsel  = ((uint32_t)(lid >> 3) & 1) * 16;

    grid_sync();

    for (int t = 0; t <= SS; t++) {
        const int rp  = t & 1;
        const int wpl = rp ^ 1;
        const __nv_bfloat16* Phi = g_Ahi[rp];
        const __nv_bfloat16* Plo = g_Alo[rp];

        float acc[3][4];
        #pragma unroll
        for (int n = 0; n < 3; n++)
            #pragma unroll
            for (int i = 0; i < 4; i++) acc[n][i] = 0.f;

        // ---- prologue: chunks 0,1 ----
        #pragma unroll
        for (int pc = 0; pc < 2; pc++) {
            uint32_t abase = sb + SM_A + pc * 32768;
            #pragma unroll
            for (int i = 0; i < 8; i++) {
                int s = i * TPB + tid;
                int split = s >> 10, rem = s & 1023;
                int row = rem >> 3, seg = rem & 7;
                cpa16(abase + split * 16384 + SWZ((uint32_t)row * 128 + seg * 16),
                      (split ? Plo : Phi) + row * HID + pc * 64 + seg * 8);
            }
            asm volatile("cp.async.commit_group;" ::: "memory");
        }

        // ---- chunk loop ----
        for (int c = 0; c < NCHUNK; c++) {
            __syncthreads();                       // prev compute done before reuse
            if (c + 2 < NCHUNK) {
                int lc = c + 2;
                uint32_t abase = sb + SM_A + (lc % 3) * 32768;
                #pragma unroll
                for (int i = 0; i < 8; i++) {
                    int s = i * TPB + tid;
                    int split = s >> 10, rem = s & 1023;
                    int row = rem >> 3, seg = rem & 7;
                    cpa16(abase + split * 16384 + SWZ((uint32_t)row * 128 + seg * 16),
                          (split ? Plo : Phi) + row * HID + lc * 64 + seg * 8);
                }
                asm volatile("cp.async.commit_group;" ::: "memory");
                asm volatile("cp.async.wait_group 2;" ::: "memory");
            } else if (c + 1 < NCHUNK) {
                asm volatile("cp.async.wait_group 1;" ::: "memory");
            } else {
                asm volatile("cp.async.wait_group 0;" ::: "memory");
            }
            __syncthreads();

            // compute chunk c
            uint32_t abase = sb + SM_A + (c % 3) * 32768;
            uint32_t ahi[4][4], alo[4][4];
            #pragma unroll
            for (int ks = 0; ks < 4; ks++) {
                uint32_t off = SWZ(aoff0 + (uint32_t)ks * 32);
                ldsm4(ahi[ks], abase + off);
                ldsm4(alo[ks], abase + 16384 + off);
            }
            uint32_t wb = sb + SM_W + (uint32_t)c * 3072;
            #pragma unroll
            for (int nt = 0; nt < 3; nt++) {
                uint32_t brow = ((uint32_t)(nt * 8 + (lid & 7))) * 128;
                #pragma unroll
                for (int ks = 0; ks < 4; ks++) {
                    uint32_t boff = SWZ(brow + (uint32_t)ks * 32 + bsel);
                    uint32_t bh[2], bl[2];
                    ldsm2(bh, wb + boff);
                    ldsm2(bl, wb + WPLANE + boff);
                    mma_bf16(acc[nt], ahi[ks], bh);
                    mma_bf16(acc[nt], alo[ks], bh);
                    mma_bf16(acc[nt], ahi[ks], bl);
                }
            }
        }

        // ---- epilogue ----
        __syncthreads();
        if (wid >= 4) {                       // rows 64-127: h1(t-2)@Whh1 partial
            int b = (wid - 4) * 16 + (lid >> 2);
            scratch[b * 8 + ejj]           = acc[2][0];
            scratch[b * 8 + ejj + 1]       = acc[2][1];
            scratch[(b + 8) * 8 + ejj]     = acc[2][2];
            scratch[(b + 8) * 8 + ejj + 1] = acc[2][3];
        }
        __syncthreads();
        if (wid < 4) {                        // rows 0-63 = batch b
            int b0 = wid * 16 + (lid >> 2);
            #pragma unroll
            for (int rr = 0; rr < 2; rr++) {
                int row = b0 + rr * 8;
                int i0  = rr * 2;
                float h1a = tanhf(acc[1][i0]     + scratch[row * 8 + ejj]     + biasv.x);
                float h1b = tanhf(acc[1][i0 + 1] + scratch[row * 8 + ejj + 1] + biasv.y);
                if (t < SS) {
                    float2 xe = __ldcg(reinterpret_cast<const float2*>(
                        &g_xe0[((size_t)t * BB + row) * HID + jg + ejj]));
                    float h0a = tanhf(acc[0][i0]     + xe.x);
                    float h0b = tanhf(acc[0][i0 + 1] + xe.y);
                    size_t e0 = (size_t)row * HID + jg + ejj;
                    __stcg(reinterpret_cast<uint32_t*>(&g_Ahi[wpl][e0]), pack_hi2(h0a, h0b));
                    __stcg(reinterpret_cast<uint32_t*>(&g_Alo[wpl][e0]), pack_lo2(h0a, h0b));
                    if (t > 0) {
                        size_t e1 = (size_t)(64 + row) * HID + jg + ejj;
                        __stcg(reinterpret_cast<uint32_t*>(&g_Ahi[wpl][e1]), pack_hi2(h1a, h1b));
                        __stcg(reinterpret_cast<uint32_t*>(&g_Alo[wpl][e1]), pack_lo2(h1a, h1b));
                    }
                } else {
                    float2 o; o.x = h1a; o.y = h1b;
                    __stcg(reinterpret_cast<float2*>(
                        &g_h1fin[(size_t)row * HID + jg + ejj]), o);
                }
            }
        }
        grid_sync();
    }
}

// ---------------------------------------------------------------------------
// Kernel 3: out[b][o] = g_h1fin[b][.] . W_out[.][o] + b_out[o]
// ---------------------------------------------------------------------------
__global__ void __launch_bounds__(128)
out_kernel(const float* __restrict__ Wout, const float* __restrict__ bout,
           float* __restrict__ out) {
    const int tid = threadIdx.x;
    const int b = tid & 63;
    const int o = tid >> 6;
    const float* h = g_h1fin + (size_t)b * HID;
    float s0 = 0.f, s1 = 0.f, s2 = 0.f, s3 = 0.f;
    #pragma unroll 4
    for (int k = 0; k < HID; k += 4) {
        s0 = fmaf(h[k + 0], Wout[(size_t)(k + 0) * NOUT + o], s0);
        s1 = fmaf(h[k + 1], Wout[(size_t)(k + 1) * NOUT + o], s1);
        s2 = fmaf(h[k + 2], Wout[(size_t)(k + 2) * NOUT + o], s2);
        s3 = fmaf(h[k + 3], Wout[(size_t)(k + 3) * NOUT + o], s3);
    }
    out[b * NOUT + o] = s0 + s1 + s2 + s3 + bout[o];
}

// ---------------------------------------------------------------------------
extern "C" void kernel_launch(void* const* d_in, const int* in_sizes, int n_in,
                              void* d_out, int out_size) {
    const int*   x    = (const int*)  d_in[0];
    const float* emb  = (const float*)d_in[1];
    const float* Wih0 = (const float*)d_in[2];
    const float* Whh0 = (const float*)d_in[3];
    const float* bhh0 = (const float*)d_in[4];
    const float* Wih1 = (const float*)d_in[5];
    const float* Whh1 = (const float*)d_in[6];
    const float* bhh1 = (const float*)d_in[7];
    const float* Wout = (const float*)d_in[8];
    const float* bout = (const float*)d_in[9];
    float* out = (float*)d_out;

    cudaFuncSetAttribute(rnn_kernel, cudaFuncAttributeMaxDynamicSharedMemorySize,
                         SMEM_BYTES);

    emb_gemm_kernel<<<dim3(SS, HID / 64), 256>>>(x, emb, Wih0, bhh0);
    rnn_kernel<<<NB, TPB, SMEM_BYTES>>>(Whh0, Wih1, Whh1, bhh1);
    out_kernel<<<1, 128>>>(Wout, bout, out);
}

// round 9
// speedup vs baseline: 2.1126x; 1.3841x over previous
#include <cuda_runtime.h>
#include <cuda_bf16.h>
#include <math.h>
#include <stdint.h>

#define BB    64
#define SS    512
#define EMBD  512
#define HID   1024
#define NOUT  2

#define NB      128
#define TPB     256
#define JW      8        // output cols per CTA
#define NCHUNK  16       // K chunks of 64
#define NSLOT   3

// SMEM map (bytes)
#define SM_W    0                      // B weights: 2 planes x 49152
#define WPLANE  49152                  // [kc 16][row 24][128B swizzled row]
#define SM_A    (2*WPLANE)             // per-warp: 3 slots x 4KB (hi 2KB + lo 2KB)
#define SM_SCR  (SM_A + 8*NSLOT*4096)  // 64x8 floats
#define SMEM_BYTES (SM_SCR + 2048)

#define SWZ(o) ((uint32_t)(o) ^ ((((uint32_t)(o))>>3)&0x70))

// ---------------------------------------------------------------------------
__device__ __align__(16) float g_xe0[(size_t)SS * BB * HID];   // [t][b][j]
__device__ __align__(16) __nv_bfloat16 g_Ahi[2][128 * HID];    // rows 0-63 h0, 64-127 h1
__device__ __align__(16) __nv_bfloat16 g_Alo[2][128 * HID];
__device__ __align__(16) float g_h1fin[BB * HID];
__device__ unsigned g_bar, g_gen;

// ---------------------------------------------------------------------------
__device__ __forceinline__ uint32_t smem_u32(const void* p) {
    return (uint32_t)__cvta_generic_to_shared(p);
}
__device__ __forceinline__ void cpa16(uint32_t dst, const void* src) {
    asm volatile("cp.async.cg.shared.global [%0], [%1], 16;"
                 :: "r"(dst), "l"(__cvta_generic_to_global(src)) : "memory");
}
__device__ __forceinline__ void ldsm4(uint32_t* r, uint32_t addr) {
    asm volatile("ldmatrix.sync.aligned.m8n8.x4.shared.b16 {%0,%1,%2,%3}, [%4];"
                 : "=r"(r[0]), "=r"(r[1]), "=r"(r[2]), "=r"(r[3]) : "r"(addr));
}
__device__ __forceinline__ void ldsm2(uint32_t* r, uint32_t addr) {
    asm volatile("ldmatrix.sync.aligned.m8n8.x2.shared.b16 {%0,%1}, [%2];"
                 : "=r"(r[0]), "=r"(r[1]) : "r"(addr));
}
__device__ __forceinline__ void mma_bf16(float* c, const uint32_t* a,
                                         const uint32_t* b) {
    asm volatile(
        "mma.sync.aligned.m16n8k16.row.col.f32.bf16.bf16.f32 "
        "{%0,%1,%2,%3}, {%4,%5,%6,%7}, {%8,%9}, {%0,%1,%2,%3};"
        : "+f"(c[0]), "+f"(c[1]), "+f"(c[2]), "+f"(c[3])
        : "r"(a[0]), "r"(a[1]), "r"(a[2]), "r"(a[3]), "r"(b[0]), "r"(b[1]));
}
__device__ __forceinline__ uint32_t pack_hi2(float a, float b) {
    __nv_bfloat16 ha = __float2bfloat16(a), hb = __float2bfloat16(b);
    return (uint32_t)*reinterpret_cast<unsigned short*>(&ha)
         | ((uint32_t)*reinterpret_cast<unsigned short*>(&hb) << 16);
}
__device__ __forceinline__ uint32_t pack_lo2(float a, float b) {
    __nv_bfloat16 ha = __float2bfloat16(a), hb = __float2bfloat16(b);
    __nv_bfloat16 la = __float2bfloat16(a - __bfloat162float(ha));
    __nv_bfloat16 lb = __float2bfloat16(b - __bfloat162float(hb));
    return (uint32_t)*reinterpret_cast<unsigned short*>(&la)
         | ((uint32_t)*reinterpret_cast<unsigned short*>(&lb) << 16);
}

__device__ __forceinline__ void grid_sync() {
    __threadfence();
    __syncthreads();
    if (threadIdx.x == 0) {
        volatile unsigned* genp = &g_gen;
        unsigned my = *genp;
        if (atomicAdd(&g_bar, 1u) == NB - 1) {
            atomicExch(&g_bar, 0u);
            __threadfence();
            atomicAdd(&g_gen, 1u);
        } else {
            while (*genp == my) { __nanosleep(32); }
        }
    }
    __syncthreads();
}

// ---------------------------------------------------------------------------
// Kernel 1: xe0[t][b][j] = emb[x[b][t]] @ W_ih0 + b_hh0
// ---------------------------------------------------------------------------
__global__ void __launch_bounds__(256)
emb_gemm_kernel(const int* __restrict__ x, const float* __restrict__ emb,
                const float* __restrict__ Wih0, const float* __restrict__ bhh0) {
    __shared__ float As[64][17];
    __shared__ float Bs[16][64];
    __shared__ int   ids[64];

    const int t   = blockIdx.x;
    const int j0  = blockIdx.y * 64;
    const int tid = threadIdx.x;

    if (tid < 64) ids[tid] = x[tid * SS + t];
    __syncthreads();

    const int ty = tid >> 4;
    const int tx = tid & 15;
    float acc[4][4];
    #pragma unroll
    for (int i = 0; i < 4; i++)
        #pragma unroll
        for (int j = 0; j < 4; j++) acc[i][j] = 0.f;

    for (int k0 = 0; k0 < EMBD; k0 += 16) {
        #pragma unroll
        for (int p = 0; p < 4; p++) {
            int r  = (tid >> 4) + p * 16;
            int kk = tid & 15;
            As[r][kk] = emb[(size_t)ids[r] * EMBD + k0 + kk];
        }
        #pragma unroll
        for (int p = 0; p < 4; p++) {
            int kk = (tid >> 6) + p * 4;
            int c  = tid & 63;
            Bs[kk][c] = Wih0[(size_t)(k0 + kk) * HID + j0 + c];
        }
        __syncthreads();
        #pragma unroll
        for (int kk = 0; kk < 16; kk++) {
            float a0 = As[ty * 4 + 0][kk];
            float a1 = As[ty * 4 + 1][kk];
            float a2 = As[ty * 4 + 2][kk];
            float a3 = As[ty * 4 + 3][kk];
            float4 bv = *reinterpret_cast<const float4*>(&Bs[kk][tx * 4]);
            float bw[4] = {bv.x, bv.y, bv.z, bv.w};
            #pragma unroll
            for (int j = 0; j < 4; j++) {
                acc[0][j] = fmaf(a0, bw[j], acc[0][j]);
                acc[1][j] = fmaf(a1, bw[j], acc[1][j]);
                acc[2][j] = fmaf(a2, bw[j], acc[2][j]);
                acc[3][j] = fmaf(a3, bw[j], acc[3][j]);
            }
        }
        __syncthreads();
    }

    float4 bv = *reinterpret_cast<const float4*>(bhh0 + j0 + tx * 4);
    #pragma unroll
    for (int i = 0; i < 4; i++) {
        float4 v;
        v.x = acc[i][0] + bv.x;
        v.y = acc[i][1] + bv.y;
        v.z = acc[i][2] + bv.z;
        v.w = acc[i][3] + bv.w;
        *reinterpret_cast<float4*>(
            &g_xe0[((size_t)t * BB + (ty * 4 + i)) * HID + j0 + tx * 4]) = v;
    }
}

// ---------------------------------------------------------------------------
// Kernel 2: persistent HMMA recurrent kernel, warp-private pipeline.
// A = [h0(t-1); h1(t-2)] (M=128). Warp w owns A rows 16w..16w+15 and loads
// them itself (cp.async groups are per-warp; no block syncs in chunk loop).
// Warps 0-3 (h0 rows) compute N-tiles {Whh0, Wih1}; warps 4-7 (h1 rows)
// compute {Whh1} only — dead output rows are never computed.
// ---------------------------------------------------------------------------
__global__ void __launch_bounds__(TPB, 1)
rnn_kernel(const float* __restrict__ Whh0, const float* __restrict__ Wih1,
           const float* __restrict__ Whh1, const float* __restrict__ bhh1) {
    extern __shared__ char smem[];
    const uint32_t sb = smem_u32(smem);
    float* scratch = reinterpret_cast<float*>(smem + SM_SCR);
    const int tid = threadIdx.x;
    const int wid = tid >> 5;
    const int lid = tid & 31;
    const int bid = blockIdx.x;
    const int jg  = bid * JW;

    // ---- resident weights: [plane][kc][row24][swizzled 128B row] ----
    for (int i = tid; i < 24 * HID; i += TPB) {
        int j24 = i / HID, k = i % HID;
        int m = j24 >> 3, jj = j24 & 7;
        const float* W = (m == 0) ? Whh0 : ((m == 1) ? Wih1 : Whh1);
        float w = W[(size_t)k * HID + jg + jj];
        __nv_bfloat16 hi = __float2bfloat16(w);
        __nv_bfloat16 lo = __float2bfloat16(w - __bfloat162float(hi));
        uint32_t off = (uint32_t)(k >> 6) * 3072 + SWZ((uint32_t)j24 * 128 + (k & 63) * 2);
        *reinterpret_cast<__nv_bfloat16*>(smem + SM_W + off) = hi;
        *reinterpret_cast<__nv_bfloat16*>(smem + SM_W + WPLANE + off) = lo;
    }
    // ---- zero A planes (both parities) ----
    for (int i = bid * TPB + tid; i < 128 * HID; i += NB * TPB) {
        g_Ahi[0][i] = __float2bfloat16(0.f); g_Ahi[1][i] = __float2bfloat16(0.f);
        g_Alo[0][i] = __float2bfloat16(0.f); g_Alo[1][i] = __float2bfloat16(0.f);
    }

    // per-lane constants
    const int ejj = (lid & 3) * 2;
    float2 biasv = *reinterpret_cast<const float2*>(bhh1 + jg + ejj);
    const uint32_t awarp = sb + SM_A + (uint32_t)wid * (NSLOT * 4096);
    const uint32_t aoff  = (uint32_t)(lid & 15) * 128 + ((uint32_t)(lid >> 4)) * 16;
    const uint32_t bsel  = ((uint32_t)(lid >> 3) & 1) * 16;
    const int lrow = lid >> 3, lseg = lid & 7;       // per-lane cp.async coords

    grid_sync();

    for (int t = 0; t <= SS; t++) {
        const int rp  = t & 1;
        const int wpl = rp ^ 1;
        const __nv_bfloat16* Phi = g_Ahi[rp] + (size_t)(wid * 16) * HID;
        const __nv_bfloat16* Plo = g_Alo[rp] + (size_t)(wid * 16) * HID;

        // prefetch epilogue xe0 (warps 0-3)
        float2 xe[2];
        if (wid < 4) {
            const int tl = (t < SS) ? t : (SS - 1);
            const int b0 = wid * 16 + (lid >> 2);
            xe[0] = __ldcg(reinterpret_cast<const float2*>(
                &g_xe0[((size_t)tl * BB + b0) * HID + jg + ejj]));
            xe[1] = __ldcg(reinterpret_cast<const float2*>(
                &g_xe0[((size_t)tl * BB + b0 + 8) * HID + jg + ejj]));
        }

        float acc0[4] = {0.f, 0.f, 0.f, 0.f};
        float acc1[4] = {0.f, 0.f, 0.f, 0.f};
        float acc2[4] = {0.f, 0.f, 0.f, 0.f};

        // ---- warp-private prologue: chunks 0,1 ----
        #pragma unroll
        for (int pc = 0; pc < 2; pc++) {
            uint32_t abase = awarp + pc * 4096;
            #pragma unroll
            for (int i = 0; i < 4; i++) {
                int r = lrow + i * 4;
                uint32_t d = SWZ((uint32_t)r * 128 + lseg * 16);
                const __nv_bfloat16* s = Phi + r * HID + pc * 64 + lseg * 8;
                cpa16(abase + d, s);
                cpa16(abase + 2048 + d, Plo + r * HID + pc * 64 + lseg * 8);
            }
            asm volatile("cp.async.commit_group;" ::: "memory");
        }

        // ---- chunk loop (no block syncs) ----
        for (int c = 0; c < NCHUNK; c++) {
            if (c + 2 < NCHUNK) {
                int lc = c + 2;
                uint32_t abase = awarp + (lc % 3) * 4096;
                #pragma unroll
                for (int i = 0; i < 4; i++) {
                    int r = lrow + i * 4;
                    uint32_t d = SWZ((uint32_t)r * 128 + lseg * 16);
                    cpa16(abase + d, Phi + r * HID + lc * 64 + lseg * 8);
                    cpa16(abase + 2048 + d, Plo + r * HID + lc * 64 + lseg * 8);
                }
                asm volatile("cp.async.commit_group;" ::: "memory");
                asm volatile("cp.async.wait_group 2;" ::: "memory");
            } else if (c + 1 < NCHUNK) {
                asm volatile("cp.async.wait_group 1;" ::: "memory");
            } else {
                asm volatile("cp.async.wait_group 0;" ::: "memory");
            }
            __syncwarp();

            uint32_t abase = awarp + (c % 3) * 4096;
            uint32_t ahi[4][4], alo[4][4];
            #pragma unroll
            for (int ks = 0; ks < 4; ks++) {
                uint32_t off = SWZ(aoff + (uint32_t)ks * 32);
                ldsm4(ahi[ks], abase + off);
                ldsm4(alo[ks], abase + 2048 + off);
            }
            uint32_t wb = sb + SM_W + (uint32_t)c * 3072;
            if (wid < 4) {
                #pragma unroll
                for (int nt = 0; nt < 2; nt++) {
                    float* acc = nt ? acc1 : acc0;
                    uint32_t brow = ((uint32_t)(nt * 8 + (lid & 7))) * 128;
                    #pragma unroll
                    for (int ks = 0; ks < 4; ks++) {
                        uint32_t boff = SWZ(brow + (uint32_t)ks * 32 + bsel);
                        uint32_t bh[2], bl[2];
                        ldsm2(bh, wb + boff);
                        ldsm2(bl, wb + WPLANE + boff);
                        mma_bf16(acc, ahi[ks], bh);
                        mma_bf16(acc, alo[ks], bh);
                        mma_bf16(acc, ahi[ks], bl);
                    }
                }
            } else {
                uint32_t brow = ((uint32_t)(16 + (lid & 7))) * 128;
                #pragma unroll
                for (int ks = 0; ks < 4; ks++) {
                    uint32_t boff = SWZ(brow + (uint32_t)ks * 32 + bsel);
                    uint32_t bh[2], bl[2];
                    ldsm2(bh, wb + boff);
                    ldsm2(bl, wb + WPLANE + boff);
                    mma_bf16(acc2, ahi[ks], bh);
                    mma_bf16(acc2, alo[ks], bh);
                    mma_bf16(acc2, ahi[ks], bl);
                }
            }
        }

        // ---- epilogue ----
        __syncthreads();
        if (wid >= 4) {                       // rows 64-127: h1(t-2)@Whh1 partial
            int b = (wid - 4) * 16 + (lid >> 2);
            scratch[b * 8 + ejj]           = acc2[0];
            scratch[b * 8 + ejj + 1]       = acc2[1];
            scratch[(b + 8) * 8 + ejj]     = acc2[2];
            scratch[(b + 8) * 8 + ejj + 1] = acc2[3];
        }
        __syncthreads();
        if (wid < 4) {                        // rows 0-63 = batch b
            int b0 = wid * 16 + (lid >> 2);
            #pragma unroll
            for (int rr = 0; rr < 2; rr++) {
                int row = b0 + rr * 8;
                int i0  = rr * 2;
                float h1a = tanhf(acc1[i0]     + scratch[row * 8 + ejj]     + biasv.x);
                float h1b = tanhf(acc1[i0 + 1] + scratch[row * 8 + ejj + 1] + biasv.y);
                if (t < SS) {
                    float h0a = tanhf(acc0[i0]     + xe[rr].x);
                    float h0b = tanhf(acc0[i0 + 1] + xe[rr].y);
                    size_t e0 = (size_t)row * HID + jg + ejj;
                    __stcg(reinterpret_cast<uint32_t*>(&g_Ahi[wpl][e0]), pack_hi2(h0a, h0b));
                    __stcg(reinterpret_cast<uint32_t*>(&g_Alo[wpl][e0]), pack_lo2(h0a, h0b));
                    if (t > 0) {
                        size_t e1 = (size_t)(64 + row) * HID + jg + ejj;
                        __stcg(reinterpret_cast<uint32_t*>(&g_Ahi[wpl][e1]), pack_hi2(h1a, h1b));
                        __stcg(reinterpret_cast<uint32_t*>(&g_Alo[wpl][e1]), pack_lo2(h1a, h1b));
                    }
                } else {
                    float2 o; o.x = h1a; o.y = h1b;
                    __stcg(reinterpret_cast<float2*>(
                        &g_h1fin[(size_t)row * HID + jg + ejj]), o);
                }
            }
        }
        grid_sync();
    }
}

// ---------------------------------------------------------------------------
// Kernel 3: out[b][o] = g_h1fin[b][.] . W_out[.][o] + b_out[o]
// ---------------------------------------------------------------------------
__global__ void __launch_bounds__(128)
out_kernel(const float* __restrict__ Wout, const float* __restrict__ bout,
           float* __restrict__ out) {
    const int tid = threadIdx.x;
    const int b = tid & 63;
    const int o = tid >> 6;
    const float* h = g_h1fin + (size_t)b * HID;
    float s0 = 0.f, s1 = 0.f, s2 = 0.f, s3 = 0.f;
    #pragma unroll 4
    for (int k = 0; k < HID; k += 4) {
        s0 = fmaf(h[k + 0], Wout[(size_t)(k + 0) * NOUT + o], s0);
        s1 = fmaf(h[k + 1], Wout[(size_t)(k + 1) * NOUT + o], s1);
        s2 = fmaf(h[k + 2], Wout[(size_t)(k + 2) * NOUT + o], s2);
        s3 = fmaf(h[k + 3], Wout[(size_t)(k + 3) * NOUT + o], s3);
    }
    out[b * NOUT + o] = s0 + s1 + s2 + s3 + bout[o];
}

// ---------------------------------------------------------------------------
extern "C" void kernel_launch(void* const* d_in, const int* in_sizes, int n_in,
                              void* d_out, int out_size) {
    const int*   x    = (const int*)  d_in[0];
    const float* emb  = (const float*)d_in[1];
    const float* Wih0 = (const float*)d_in[2];
    const float* Whh0 = (const float*)d_in[3];
    const float* bhh0 = (const float*)d_in[4];
    const float* Wih1 = (const float*)d_in[5];
    const float* Whh1 = (const float*)d_in[6];
    const float* bhh1 = (const float*)d_in[7];
    const float* Wout = (const float*)d_in[8];
    const float* bout = (const float*)d_in[9];
    float* out = (float*)d_out;

    cudaFuncSetAttribute(rnn_kernel, cudaFuncAttributeMaxDynamicSharedMemorySize,
                         SMEM_BYTES);

    emb_gemm_kernel<<<dim3(SS, HID / 64), 256>>>(x, emb, Wih0, bhh0);
    rnn_kernel<<<NB, TPB, SMEM_BYTES>>>(Whh0, Wih1, Whh1, bhh1);
    out_kernel<<<1, 128>>>(Wout, bout, out);
}

// round 11
// speedup vs baseline: 2.6479x; 1.2534x over previous
#include <cuda_runtime.h>
#include <cuda_fp16.h>
#include <cuda_bf16.h>
#include <math.h>
#include <stdint.h>

#define BB    64
#define SS    512
#define EMBD  512
#define HID   1024
#define NOUT  2

#define NB      128
#define TPB     256
#define JW      8        // output cols per CTA
#define NCHUNK  16       // K chunks of 64
#define NSLOT   4

#define WLSCALE 2048.0f
#define WLINV   (1.0f / 2048.0f)

// SMEM map (bytes)
#define SM_W    0                      // W: 2 fp16 planes x 49152 (Wh, Wl*2048)
#define WPLANE  49152                  // [kc 16][row 24][128B swizzled row]
#define SM_A    (2*WPLANE)             // per-warp: 4 slots x 2KB (single fp16 plane)
#define SM_SCR  (SM_A + 8*NSLOT*2048)  // 64x8 floats
#define SMEM_BYTES (SM_SCR + 2048)

#define SWZ(o) ((uint32_t)(o) ^ ((((uint32_t)(o))>>3)&0x70))

// ---------------------------------------------------------------------------
__device__ __align__(16) float g_xe0[(size_t)SS * BB * HID];   // [t][b][j]
__device__ __align__(16) __half g_A[2][128 * HID];             // rows 0-63 h0, 64-127 h1
__device__ __align__(16) float g_h1fin[BB * HID];
__device__ unsigned g_bar, g_gen;

// ---------------------------------------------------------------------------
__device__ __forceinline__ uint32_t smem_u32(const void* p) {
    return (uint32_t)__cvta_generic_to_shared(p);
}
__device__ __forceinline__ void cpa16(uint32_t dst, const void* src) {
    asm volatile("cp.async.cg.shared.global [%0], [%1], 16;"
                 :: "r"(dst), "l"(__cvta_generic_to_global(src)) : "memory");
}
__device__ __forceinline__ void ldsm4(uint32_t* r, uint32_t addr) {
    asm volatile("ldmatrix.sync.aligned.m8n8.x4.shared.b16 {%0,%1,%2,%3}, [%4];"
                 : "=r"(r[0]), "=r"(r[1]), "=r"(r[2]), "=r"(r[3]) : "r"(addr));
}
__device__ __forceinline__ void ldsm2(uint32_t* r, uint32_t addr) {
    asm volatile("ldmatrix.sync.aligned.m8n8.x2.shared.b16 {%0,%1}, [%2];"
                 : "=r"(r[0]), "=r"(r[1]) : "r"(addr));
}
__device__ __forceinline__ void mma_f16(float* c, const uint32_t* a,
                                        const uint32_t* b) {
    asm volatile(
        "mma.sync.aligned.m16n8k16.row.col.f32.f16.f16.f32 "
        "{%0,%1,%2,%3}, {%4,%5,%6,%7}, {%8,%9}, {%0,%1,%2,%3};"
        : "+f"(c[0]), "+f"(c[1]), "+f"(c[2]), "+f"(c[3])
        : "r"(a[0]), "r"(a[1]), "r"(a[2]), "r"(a[3]), "r"(b[0]), "r"(b[1]));
}
__device__ __forceinline__ uint32_t pack2h(float a, float b) {
    __half2 h = __floats2half2_rn(a, b);
    return *reinterpret_cast<uint32_t*>(&h);
}

__device__ __forceinline__ void grid_sync() {
    __threadfence();
    __syncthreads();
    if (threadIdx.x == 0) {
        volatile unsigned* genp = &g_gen;
        unsigned my = *genp;
        if (atomicAdd(&g_bar, 1u) == NB - 1) {
            atomicExch(&g_bar, 0u);
            __threadfence();
            atomicAdd(&g_gen, 1u);
        } else {
            while (*genp == my) { __nanosleep(32); }
        }
    }
    __syncthreads();
}

// ---------------------------------------------------------------------------
// Kernel 1: xe0[t][b][j] = emb[x[b][t]] @ W_ih0 + b_hh0
// ---------------------------------------------------------------------------
__global__ void __launch_bounds__(256)
emb_gemm_kernel(const int* __restrict__ x, const float* __restrict__ emb,
                const float* __restrict__ Wih0, const float* __restrict__ bhh0) {
    __shared__ float As[64][17];
    __shared__ float Bs[16][64];
    __shared__ int   ids[64];

    const int t   = blockIdx.x;
    const int j0  = blockIdx.y * 64;
    const int tid = threadIdx.x;

    if (tid < 64) ids[tid] = x[tid * SS + t];
    __syncthreads();

    const int ty = tid >> 4;
    const int tx = tid & 15;
    float acc[4][4];
    #pragma unroll
    for (int i = 0; i < 4; i++)
        #pragma unroll
        for (int j = 0; j < 4; j++) acc[i][j] = 0.f;

    for (int k0 = 0; k0 < EMBD; k0 += 16) {
        #pragma unroll
        for (int p = 0; p < 4; p++) {
            int r  = (tid >> 4) + p * 16;
            int kk = tid & 15;
            As[r][kk] = emb[(size_t)ids[r] * EMBD + k0 + kk];
        }
        #pragma unroll
        for (int p = 0; p < 4; p++) {
            int kk = (tid >> 6) + p * 4;
            int c  = tid & 63;
            Bs[kk][c] = Wih0[(size_t)(k0 + kk) * HID + j0 + c];
        }
        __syncthreads();
        #pragma unroll
        for (int kk = 0; kk < 16; kk++) {
            float a0 = As[ty * 4 + 0][kk];
            float a1 = As[ty * 4 + 1][kk];
            float a2 = As[ty * 4 + 2][kk];
            float a3 = As[ty * 4 + 3][kk];
            float4 bv = *reinterpret_cast<const float4*>(&Bs[kk][tx * 4]);
            float bw[4] = {bv.x, bv.y, bv.z, bv.w};
            #pragma unroll
            for (int j = 0; j < 4; j++) {
                acc[0][j] = fmaf(a0, bw[j], acc[0][j]);
                acc[1][j] = fmaf(a1, bw[j], acc[1][j]);
                acc[2][j] = fmaf(a2, bw[j], acc[2][j]);
                acc[3][j] = fmaf(a3, bw[j], acc[3][j]);
            }
        }
        __syncthreads();
    }

    float4 bv = *reinterpret_cast<const float4*>(bhh0 + j0 + tx * 4);
    #pragma unroll
    for (int i = 0; i < 4; i++) {
        float4 v;
        v.x = acc[i][0] + bv.x;
        v.y = acc[i][1] + bv.y;
        v.z = acc[i][2] + bv.z;
        v.w = acc[i][3] + bv.w;
        *reinterpret_cast<float4*>(
            &g_xe0[((size_t)t * BB + (ty * 4 + i)) * HID + j0 + tx * 4]) = v;
    }
}

// ---------------------------------------------------------------------------
// Kernel 2: persistent HMMA recurrent kernel, fp16 single-plane A.
// A = [h0(t-1); h1(t-2)] (M=128) stored as ONE fp16 plane (h error 2^-12).
// W in 2 fp16 planes: Wh + Wl*2048 (Wl scaled out of fp16-subnormal range;
// unscaled by 1/2048 at epilogue). 2 MMA products per tile: A*Wh, A*Wl.
// Warp w owns A rows 16w..16w+15 with a private cp.async 4-slot ring; no
// block syncs inside the chunk loop. Warps 0-3 compute {Whh0,Wih1} tiles,
// warps 4-7 compute {Whh1} only.
// ---------------------------------------------------------------------------
__global__ void __launch_bounds__(TPB, 1)
rnn_kernel(const float* __restrict__ Whh0, const float* __restrict__ Wih1,
           const float* __restrict__ Whh1, const float* __restrict__ bhh1) {
    extern __shared__ char smem[];
    const uint32_t sb = smem_u32(smem);
    float* scratch = reinterpret_cast<float*>(smem + SM_SCR);
    const int tid = threadIdx.x;
    const int wid = tid >> 5;
    const int lid = tid & 31;
    const int bid = blockIdx.x;
    const int jg  = bid * JW;

    // ---- resident weights: [plane][kc][row24][swizzled 128B row] ----
    for (int i = tid; i < 24 * HID; i += TPB) {
        int j24 = i / HID, k = i % HID;
        int m = j24 >> 3, jj = j24 & 7;
        const float* W = (m == 0) ? Whh0 : ((m == 1) ? Wih1 : Whh1);
        float w = W[(size_t)k * HID + jg + jj];
        __half hi = __float2half_rn(w);
        __half lo = __float2half_rn((w - __half2float(hi)) * WLSCALE);
        uint32_t off = (uint32_t)(k >> 6) * 3072 + SWZ((uint32_t)j24 * 128 + (k & 63) * 2);
        *reinterpret_cast<__half*>(smem + SM_W + off) = hi;
        *reinterpret_cast<__half*>(smem + SM_W + WPLANE + off) = lo;
    }
    // ---- zero A plane (both parities) ----
    for (int i = bid * TPB + tid; i < 128 * HID; i += NB * TPB) {
        g_A[0][i] = __float2half(0.f);
        g_A[1][i] = __float2half(0.f);
    }

    // per-lane constants
    const int ejj = (lid & 3) * 2;
    float2 biasv = *reinterpret_cast<const float2*>(bhh1 + jg + ejj);
    const uint32_t awarp = sb + SM_A + (uint32_t)wid * (NSLOT * 2048);
    const uint32_t aoff  = (uint32_t)(lid & 15) * 128 + ((uint32_t)(lid >> 4)) * 16;
    const uint32_t bsel  = ((uint32_t)(lid >> 3) & 1) * 16;
    const int lrow = lid >> 3, lseg = lid & 7;       // per-lane cp.async coords

    grid_sync();

    for (int t = 0; t <= SS; t++) {
        const int rp  = t & 1;
        const int wpl = rp ^ 1;
        const __half* Pa = g_A[rp] + (size_t)(wid * 16) * HID;

        // prefetch epilogue xe0 (warps 0-3)
        float2 xe[2];
        if (wid < 4) {
            const int tl = (t < SS) ? t : (SS - 1);
            const int b0 = wid * 16 + (lid >> 2);
            xe[0] = __ldcg(reinterpret_cast<const float2*>(
                &g_xe0[((size_t)tl * BB + b0) * HID + jg + ejj]));
            xe[1] = __ldcg(reinterpret_cast<const float2*>(
                &g_xe0[((size_t)tl * BB + b0 + 8) * HID + jg + ejj]));
        }

        float acc0[4] = {0.f, 0.f, 0.f, 0.f};
        float acc0l[4] = {0.f, 0.f, 0.f, 0.f};
        float acc1[4] = {0.f, 0.f, 0.f, 0.f};
        float acc1l[4] = {0.f, 0.f, 0.f, 0.f};
        float acc2[4] = {0.f, 0.f, 0.f, 0.f};
        float acc2l[4] = {0.f, 0.f, 0.f, 0.f};

        // ---- warp-private prologue: chunks 0..2 ----
        #pragma unroll
        for (int pc = 0; pc < 3; pc++) {
            uint32_t abase = awarp + pc * 2048;
            #pragma unroll
            for (int i = 0; i < 4; i++) {
                int r = lrow + i * 4;
                cpa16(abase + SWZ((uint32_t)r * 128 + lseg * 16),
                      Pa + r * HID + pc * 64 + lseg * 8);
            }
            asm volatile("cp.async.commit_group;" ::: "memory");
        }

        // ---- chunk loop (no block syncs) ----
        for (int c = 0; c < NCHUNK; c++) {
            if (c + 3 < NCHUNK) {
                int lc = c + 3;
                uint32_t abase = awarp + (lc & 3) * 2048;
                #pragma unroll
                for (int i = 0; i < 4; i++) {
                    int r = lrow + i * 4;
                    cpa16(abase + SWZ((uint32_t)r * 128 + lseg * 16),
                          Pa + r * HID + lc * 64 + lseg * 8);
                }
                asm volatile("cp.async.commit_group;" ::: "memory");
                asm volatile("cp.async.wait_group 3;" ::: "memory");
            } else if (c + 2 < NCHUNK) {
                asm volatile("cp.async.wait_group 2;" ::: "memory");
            } else if (c + 1 < NCHUNK) {
                asm volatile("cp.async.wait_group 1;" ::: "memory");
            } else {
                asm volatile("cp.async.wait_group 0;" ::: "memory");
            }
            __syncwarp();

            uint32_t abase = awarp + (c & 3) * 2048;
            uint32_t afr[4][4];
            #pragma unroll
            for (int ks = 0; ks < 4; ks++)
                ldsm4(afr[ks], abase + SWZ(aoff + (uint32_t)ks * 32));

            uint32_t wb = sb + SM_W + (uint32_t)c * 3072;
            if (wid < 4) {
                #pragma unroll
                for (int nt = 0; nt < 2; nt++) {
                    float* acc  = nt ? acc1  : acc0;
                    float* accl = nt ? acc1l : acc0l;
                    uint32_t brow = ((uint32_t)(nt * 8 + (lid & 7))) * 128;
                    #pragma unroll
                    for (int ks = 0; ks < 4; ks++) {
                        uint32_t boff = SWZ(brow + (uint32_t)ks * 32 + bsel);
                        uint32_t bh[2], bl[2];
                        ldsm2(bh, wb + boff);
                        ldsm2(bl, wb + WPLANE + boff);
                        mma_f16(acc,  afr[ks], bh);
                        mma_f16(accl, afr[ks], bl);
                    }
                }
            } else {
                uint32_t brow = ((uint32_t)(16 + (lid & 7))) * 128;
                #pragma unroll
                for (int ks = 0; ks < 4; ks++) {
                    uint32_t boff = SWZ(brow + (uint32_t)ks * 32 + bsel);
                    uint32_t bh[2], bl[2];
                    ldsm2(bh, wb + boff);
                    ldsm2(bl, wb + WPLANE + boff);
                    mma_f16(acc2,  afr[ks], bh);
                    mma_f16(acc2l, afr[ks], bl);
                }
            }
        }

        // ---- epilogue ----
        __syncthreads();
        if (wid >= 4) {                       // rows 64-127: h1(t-2)@Whh1 partial
            int b = (wid - 4) * 16 + (lid >> 2);
            scratch[b * 8 + ejj]           = fmaf(acc2l[0], WLINV, acc2[0]);
            scratch[b * 8 + ejj + 1]       = fmaf(acc2l[1], WLINV, acc2[1]);
            scratch[(b + 8) * 8 + ejj]     = fmaf(acc2l[2], WLINV, acc2[2]);
            scratch[(b + 8) * 8 + ejj + 1] = fmaf(acc2l[3], WLINV, acc2[3]);
        }
        __syncthreads();
        if (wid < 4) {                        // rows 0-63 = batch b
            int b0 = wid * 16 + (lid >> 2);
            #pragma unroll
            for (int rr = 0; rr < 2; rr++) {
                int row = b0 + rr * 8;
                int i0  = rr * 2;
                float s1a = fmaf(acc1l[i0],     WLINV, acc1[i0]);
                float s1b = fmaf(acc1l[i0 + 1], WLINV, acc1[i0 + 1]);
                float h1a = tanhf(s1a + scratch[row * 8 + ejj]     + biasv.x);
                float h1b = tanhf(s1b + scratch[row * 8 + ejj + 1] + biasv.y);
                if (t < SS) {
                    float s0a = fmaf(acc0l[i0],     WLINV, acc0[i0]);
                    float s0b = fmaf(acc0l[i0 + 1], WLINV, acc0[i0 + 1]);
                    float h0a = tanhf(s0a + xe[rr].x);
                    float h0b = tanhf(s0b + xe[rr].y);
                    size_t e0 = (size_t)row * HID + jg + ejj;
                    __stcg(reinterpret_cast<uint32_t*>(&g_A[wpl][e0]),
                           pack2h(h0a, h0b));
                    if (t > 0) {
                        size_t e1 = (size_t)(64 + row) * HID + jg + ejj;
                        __stcg(reinterpret_cast<uint32_t*>(&g_A[wpl][e1]),
                               pack2h(h1a, h1b));
                    }
                } else {
                    float2 o; o.x = h1a; o.y = h1b;
                    __stcg(reinterpret_cast<float2*>(
                        &g_h1fin[(size_t)row * HID + jg + ejj]), o);
                }
            }
        }
        grid_sync();
    }
}

// ---------------------------------------------------------------------------
// Kernel 3: out[b][o] = g_h1fin[b][.] . W_out[.][o] + b_out[o]
// ---------------------------------------------------------------------------
__global__ void __launch_bounds__(128)
out_kernel(const float* __restrict__ Wout, const float* __restrict__ bout,
           float* __restrict__ out) {
    const int tid = threadIdx.x;
    const int b = tid & 63;
    const int o = tid >> 6;
    const float* h = g_h1fin + (size_t)b * HID;
    float s0 = 0.f, s1 = 0.f, s2 = 0.f, s3 = 0.f;
    #pragma unroll 4
    for (int k = 0; k < HID; k += 4) {
        s0 = fmaf(h[k + 0], Wout[(size_t)(k + 0) * NOUT + o], s0);
        s1 = fmaf(h[k + 1], Wout[(size_t)(k + 1) * NOUT + o], s1);
        s2 = fmaf(h[k + 2], Wout[(size_t)(k + 2) * NOUT + o], s2);
        s3 = fmaf(h[k + 3], Wout[(size_t)(k + 3) * NOUT + o], s3);
    }
    out[b * NOUT + o] = s0 + s1 + s2 + s3 + bout[o];
}

// ---------------------------------------------------------------------------
extern "C" void kernel_launch(void* const* d_in, const int* in_sizes, int n_in,
                              void* d_out, int out_size) {
    const int*   x    = (const int*)  d_in[0];
    const float* emb  = (const float*)d_in[1];
    const float* Wih0 = (const float*)d_in[2];
    const float* Whh0 = (const float*)d_in[3];
    const float* bhh0 = (const float*)d_in[4];
    const float* Wih1 = (const float*)d_in[5];
    const float* Whh1 = (const float*)d_in[6];
    const float* bhh1 = (const float*)d_in[7];
    const float* Wout = (const float*)d_in[8];
    const float* bout = (const float*)d_in[9];
    float* out = (float*)d_out;

    cudaFuncSetAttribute(rnn_kernel, cudaFuncAttributeMaxDynamicSharedMemorySize,
                         SMEM_BYTES);

    emb_gemm_kernel<<<dim3(SS, HID / 64), 256>>>(x, emb, Wih0, bhh0);
    rnn_kernel<<<NB, TPB, SMEM_BYTES>>>(Whh0, Wih1, Whh1, bhh1);
    out_kernel<<<1, 128>>>(Wout, bout, out);
}